// round 3
// baseline (speedup 1.0000x reference)
#include <cuda_runtime.h>
#include <cuda_bf16.h>
#include <cstdint>
#include <math.h>

// ---------------------------------------------------------------------------
// Problem constants
// ---------------------------------------------------------------------------
#define BATCH 8192
#define TDIM  512
#define FDIM  2048
#define DQ    8
#define NATTN 4
#define NMLP  2

// ---------------------------------------------------------------------------
// Device scratch (static — no allocation at launch time)
// ---------------------------------------------------------------------------
__device__ float g_H  [BATCH * TDIM * DQ];   // 128 MB  RFF tokens
__device__ float g_Q  [BATCH * TDIM];        // 16 MB   residual stream
__device__ float g_h  [BATCH * TDIM];        // 16 MB   LN output
__device__ float g_mu [BATCH * TDIM];        // 16 MB
__device__ float g_sig[BATCH * TDIM];        // 16 MB
__device__ float g_t  [BATCH * FDIM];        // 64 MB   FFN intermediate

// ---------------------------------------------------------------------------
// Helpers
// ---------------------------------------------------------------------------
__device__ __forceinline__ float silu_f(float x) {
    return x / (1.0f + __expf(-x));
}

__device__ __forceinline__ void split_bf16(float x, __nv_bfloat16& hi, __nv_bfloat16& lo) {
    hi = __float2bfloat16_rn(x);
    lo = __float2bfloat16_rn(x - __bfloat162float(hi));
}

__device__ __forceinline__ uint32_t pack2(__nv_bfloat16 a, __nv_bfloat16 b) {
    uint32_t ua = __bfloat16_as_ushort(a);
    uint32_t ub = __bfloat16_as_ushort(b);
    return ua | (ub << 16);
}

__device__ __forceinline__ void mma_bf16(float* d, const uint32_t* a, const uint32_t* b) {
    asm volatile(
        "mma.sync.aligned.m16n8k16.row.col.f32.bf16.bf16.f32 "
        "{%0,%1,%2,%3}, {%4,%5,%6,%7}, {%8,%9}, {%0,%1,%2,%3};\n"
        : "+f"(d[0]), "+f"(d[1]), "+f"(d[2]), "+f"(d[3])
        : "r"(a[0]), "r"(a[1]), "r"(a[2]), "r"(a[3]), "r"(b[0]), "r"(b[1]));
}

// ---------------------------------------------------------------------------
// bf16x3 split GEMM: C[M,N] = epi(A[M,K] @ W[N,K]^T + bias)
//   A = Ahi + Alo (bf16 split), same for W; D += Ahi*Whi + Ahi*Wlo + Alo*Whi
//   relative error ~2^-18 (lo*lo dropped) -- effectively fp32 accurate.
// EPI: 0 = bias only, 1 = tanh(.), 2 = silu(.), 3 = . + C (residual, in place)
// Tiles: BM=128, BN=128, BK=32; 256 threads = 8 warps (2 m x 4 n), warp 64x32.
// smem stores bf16 PAIRS as uint32: 16 pairs per row per BK, stride 20 padding
// => fragment LDS bank (g*20 + tg) mod 32 distinct for all 32 lanes.
// ---------------------------------------------------------------------------
#define BM 128
#define BN 128
#define BK 32
#define SSTR 20

template<int EPI>
__global__ __launch_bounds__(256) void gemm_bf16x3(
    const float* __restrict__ A, const float* __restrict__ W,
    const float* __restrict__ bias, float* __restrict__ C,
    int M, int N, int K)
{
    __shared__ uint32_t Ahi[BM][SSTR];
    __shared__ uint32_t Alo[BM][SSTR];
    __shared__ uint32_t Whi[BN][SSTR];
    __shared__ uint32_t Wlo[BN][SSTR];

    const int tid  = threadIdx.x;
    const int lane = tid & 31;
    const int warp = tid >> 5;
    const int warpM = warp & 1;      // 0..1
    const int warpN = warp >> 1;     // 0..3
    const int g  = lane >> 2;        // groupID (0..7)
    const int tg = lane & 3;         // threadID in group (0..3)

    const int rowBase = blockIdx.y * BM;
    const int colBase = blockIdx.x * BN;

    float acc[4][4][4];
#pragma unroll
    for (int mi = 0; mi < 4; mi++)
#pragma unroll
        for (int ni = 0; ni < 4; ni++)
#pragma unroll
            for (int r = 0; r < 4; r++) acc[mi][ni][r] = 0.0f;

    for (int k0 = 0; k0 < K; k0 += BK) {
        // stage A and W tiles: each 128 rows x 32 floats = 1024 float4, 4/thread
#pragma unroll
        for (int i = 0; i < 4; i++) {
            int f4  = tid + i * 256;         // 0..1023
            int row = f4 >> 3;               // 8 float4 per row
            int c2  = (f4 & 7) * 2;          // uint32-pair column (0..15)
            float4 va = *(const float4*)(A + (size_t)(rowBase + row) * K + k0 + (f4 & 7) * 4);
            __nv_bfloat16 h0, l0, h1, l1, h2, l2, h3, l3;
            split_bf16(va.x, h0, l0); split_bf16(va.y, h1, l1);
            split_bf16(va.z, h2, l2); split_bf16(va.w, h3, l3);
            Ahi[row][c2    ] = pack2(h0, h1);
            Ahi[row][c2 + 1] = pack2(h2, h3);
            Alo[row][c2    ] = pack2(l0, l1);
            Alo[row][c2 + 1] = pack2(l2, l3);
            float4 vw = *(const float4*)(W + (size_t)(colBase + row) * K + k0 + (f4 & 7) * 4);
            split_bf16(vw.x, h0, l0); split_bf16(vw.y, h1, l1);
            split_bf16(vw.z, h2, l2); split_bf16(vw.w, h3, l3);
            Whi[row][c2    ] = pack2(h0, h1);
            Whi[row][c2 + 1] = pack2(h2, h3);
            Wlo[row][c2    ] = pack2(l0, l1);
            Wlo[row][c2 + 1] = pack2(l2, l3);
        }
        __syncthreads();

#pragma unroll
        for (int kc = 0; kc < BK / 16; kc++) {
            const int kk = kc * 8;           // uint32-pair offset
            uint32_t ahi[4][4], alo[4][4], bhi[4][2], blo[4][2];
#pragma unroll
            for (int mi = 0; mi < 4; mi++) {
                int r = warpM * 64 + mi * 16;
                ahi[mi][0] = Ahi[r + g    ][kk + tg    ];
                ahi[mi][1] = Ahi[r + g + 8][kk + tg    ];
                ahi[mi][2] = Ahi[r + g    ][kk + tg + 4];
                ahi[mi][3] = Ahi[r + g + 8][kk + tg + 4];
                alo[mi][0] = Alo[r + g    ][kk + tg    ];
                alo[mi][1] = Alo[r + g + 8][kk + tg    ];
                alo[mi][2] = Alo[r + g    ][kk + tg + 4];
                alo[mi][3] = Alo[r + g + 8][kk + tg + 4];
            }
#pragma unroll
            for (int ni = 0; ni < 4; ni++) {
                int c = warpN * 32 + ni * 8;
                bhi[ni][0] = Whi[c + g][kk + tg    ];
                bhi[ni][1] = Whi[c + g][kk + tg + 4];
                blo[ni][0] = Wlo[c + g][kk + tg    ];
                blo[ni][1] = Wlo[c + g][kk + tg + 4];
            }
#pragma unroll
            for (int mi = 0; mi < 4; mi++)
#pragma unroll
                for (int ni = 0; ni < 4; ni++) {
                    mma_bf16(acc[mi][ni], ahi[mi], bhi[ni]);
                    mma_bf16(acc[mi][ni], ahi[mi], blo[ni]);
                    mma_bf16(acc[mi][ni], alo[mi], bhi[ni]);
                }
        }
        __syncthreads();
    }

    // epilogue: c0,c1 at (m, n0..n0+1); c2,c3 at (m+8, n0..n0+1)
#pragma unroll
    for (int mi = 0; mi < 4; mi++) {
#pragma unroll
        for (int ni = 0; ni < 4; ni++) {
            int m0 = rowBase + warpM * 64 + mi * 16 + g;
            int n0 = colBase + warpN * 32 + ni * 8 + tg * 2;
            float bn0 = bias[n0], bn1 = bias[n0 + 1];
#pragma unroll
            for (int h = 0; h < 2; h++) {
                int m = m0 + h * 8;
                float v0 = acc[mi][ni][2 * h + 0] + bn0;
                float v1 = acc[mi][ni][2 * h + 1] + bn1;
                float* p = C + (size_t)m * N + n0;
                if (EPI == 1) { v0 = tanhf(v0); v1 = tanhf(v1); }
                else if (EPI == 2) { v0 = silu_f(v0); v1 = silu_f(v1); }
                else if (EPI == 3) { v0 += p[0]; v1 += p[1]; }
                p[0] = v0; p[1] = v1;
            }
        }
    }
}

// ---------------------------------------------------------------------------
// RFF tokenizer: H[b,n,k] = cos(omega[n,k,:].x[b,:] + phase[n,k])
// ---------------------------------------------------------------------------
__global__ __launch_bounds__(256) void h_kernel(
    const float* __restrict__ x, const float* __restrict__ omega,
    const float* __restrict__ phase)
{
    int idx = blockIdx.x * 256 + threadIdx.x;     // b*T + n
    int b = idx >> 9, n = idx & 511;
    float x0 = x[b * 2 + 0], x1 = x[b * 2 + 1];
    float out[8];
#pragma unroll
    for (int k = 0; k < 8; k++) {
        int nk = n * 8 + k;
        float arg = fmaf(omega[nk * 2 + 0], x0,
                    fmaf(omega[nk * 2 + 1], x1, phase[nk]));
        out[k] = cosf(arg);
    }
    float4* H4 = (float4*)(g_H + (size_t)idx * 8);
    H4[0] = make_float4(out[0], out[1], out[2], out[3]);
    H4[1] = make_float4(out[4], out[5], out[6], out[7]);
}

// ---------------------------------------------------------------------------
// Q0 = silu(x @ l1_w^T + l1_b)
// ---------------------------------------------------------------------------
__global__ __launch_bounds__(256) void q0_kernel(
    const float* __restrict__ x, const float* __restrict__ w,
    const float* __restrict__ bias)
{
    int idx = blockIdx.x * 256 + threadIdx.x;     // b*T + t
    int b = idx >> 9, t = idx & 511;
    float p = fmaf(x[b * 2 + 0], w[t * 2 + 0],
              fmaf(x[b * 2 + 1], w[t * 2 + 1], bias[t]));
    g_Q[idx] = silu_f(p);
}

// ---------------------------------------------------------------------------
// LayerNorm over T=512: one warp per row
// ---------------------------------------------------------------------------
__global__ __launch_bounds__(256) void ln_kernel(
    const float* __restrict__ X, const float* __restrict__ gam,
    const float* __restrict__ bet, float* __restrict__ Y)
{
    int warp = threadIdx.x >> 5, lane = threadIdx.x & 31;
    int row = blockIdx.x * 8 + warp;
    const float4* xr = (const float4*)(X + (size_t)row * 512);
    float4 v[4];
    float s = 0.0f;
#pragma unroll
    for (int j = 0; j < 4; j++) {
        v[j] = xr[lane + j * 32];
        s += v[j].x + v[j].y + v[j].z + v[j].w;
    }
#pragma unroll
    for (int o = 16; o > 0; o >>= 1) s += __shfl_xor_sync(0xffffffffu, s, o);
    float m = s * (1.0f / 512.0f);
    float vs = 0.0f;
#pragma unroll
    for (int j = 0; j < 4; j++) {
        float dx = v[j].x - m, dy = v[j].y - m, dz = v[j].z - m, dw = v[j].w - m;
        vs += dx * dx + dy * dy + dz * dz + dw * dw;
    }
#pragma unroll
    for (int o = 16; o > 0; o >>= 1) vs += __shfl_xor_sync(0xffffffffu, vs, o);
    float inv = rsqrtf(vs * (1.0f / 512.0f) + 1e-5f);

    float4* yr = (float4*)(Y + (size_t)row * 512);
    const float4* gr = (const float4*)gam;
    const float4* br = (const float4*)bet;
#pragma unroll
    for (int j = 0; j < 4; j++) {
        int c = lane + j * 32;
        float4 gg = gr[c], bb = br[c], o4;
        o4.x = (v[j].x - m) * inv * gg.x + bb.x;
        o4.y = (v[j].y - m) * inv * gg.y + bb.y;
        o4.z = (v[j].z - m) * inv * gg.z + bb.z;
        o4.w = (v[j].w - m) * inv * gg.w + bb.w;
        yr[c] = o4;
    }
}

// ---------------------------------------------------------------------------
// Attention gather: Q[b,n] += sum_k exp(-0.5 (G[n,k]-mu)^2/(sig^2+eps)) * H[b,n,k]
// ---------------------------------------------------------------------------
__global__ __launch_bounds__(256) void attn_kernel(const float* __restrict__ G)
{
    int idx = blockIdx.x * 256 + threadIdx.x;     // b*T + n
    int n = idx & 511;
    float mu = g_mu[idx], sg = g_sig[idx];
    float rs = 1.0f / fmaf(sg, sg, 1e-8f);
    const float4* H4 = (const float4*)(g_H + (size_t)idx * 8);
    const float4* G4 = (const float4*)(G + n * 8);
    float acc = 0.0f;
#pragma unroll
    for (int j = 0; j < 2; j++) {
        float4 h4 = H4[j], gg = G4[j];
        float d;
        d = gg.x - mu; acc += __expf(-0.5f * d * d * rs) * h4.x;
        d = gg.y - mu; acc += __expf(-0.5f * d * d * rs) * h4.y;
        d = gg.z - mu; acc += __expf(-0.5f * d * d * rs) * h4.z;
        d = gg.w - mu; acc += __expf(-0.5f * d * d * rs) * h4.w;
    }
    g_Q[idx] += acc;
}

// ---------------------------------------------------------------------------
// Readout: out[b] = sum_t silu(Q[b,t]) * ro_w[t] + ro_b
// ---------------------------------------------------------------------------
__global__ __launch_bounds__(256) void final_kernel(
    const float* __restrict__ ro_w, const float* __restrict__ ro_b,
    float* __restrict__ out)
{
    int warp = threadIdx.x >> 5, lane = threadIdx.x & 31;
    int row = blockIdx.x * 8 + warp;
    const float4* q4 = (const float4*)(g_Q + (size_t)row * 512);
    const float4* w4 = (const float4*)ro_w;
    float s = 0.0f;
#pragma unroll
    for (int j = 0; j < 4; j++) {
        int c = lane + j * 32;
        float4 q = q4[c], w = w4[c];
        s += silu_f(q.x) * w.x + silu_f(q.y) * w.y
           + silu_f(q.z) * w.z + silu_f(q.w) * w.w;
    }
#pragma unroll
    for (int o = 16; o > 0; o >>= 1) s += __shfl_xor_sync(0xffffffffu, s, o);
    if (lane == 0) out[row] = s + ro_b[0];
}

// ---------------------------------------------------------------------------
// Host launcher
// ---------------------------------------------------------------------------
static float* sym_addr(const void* sym) {
    void* p = nullptr;
    cudaGetSymbolAddress(&p, sym);
    return (float*)p;
}

extern "C" void kernel_launch(void* const* d_in, const int* in_sizes, int n_in,
                              void* d_out, int out_size)
{
    const float* x      = (const float*)d_in[0];
    const float* omega  = (const float*)d_in[1];
    const float* G      = (const float*)d_in[2];
    const float* phase  = (const float*)d_in[3];
    const float* l1_w   = (const float*)d_in[4];
    const float* l1_b   = (const float*)d_in[5];
    const float* mu_w   = (const float*)d_in[6];
    const float* mu_b   = (const float*)d_in[7];
    const float* sg_w   = (const float*)d_in[8];
    const float* sg_b   = (const float*)d_in[9];
    const float* alnqg  = (const float*)d_in[10];
    const float* alnqb  = (const float*)d_in[11];
    const float* alnfg  = (const float*)d_in[12];
    const float* alnfb  = (const float*)d_in[13];
    const float* a_w1   = (const float*)d_in[14];
    const float* a_b1   = (const float*)d_in[15];
    const float* a_w2   = (const float*)d_in[16];
    const float* a_b2   = (const float*)d_in[17];
    const float* mln_g  = (const float*)d_in[18];
    const float* mln_b  = (const float*)d_in[19];
    const float* m_w1   = (const float*)d_in[20];
    const float* m_b1   = (const float*)d_in[21];
    const float* m_w2   = (const float*)d_in[22];
    const float* m_b2   = (const float*)d_in[23];
    const float* ro_w   = (const float*)d_in[24];
    const float* ro_b   = (const float*)d_in[25];
    float* out = (float*)d_out;

    float* Q   = sym_addr(g_Q);
    float* h   = sym_addr(g_h);
    float* mu  = sym_addr(g_mu);
    float* sig = sym_addr(g_sig);
    float* t   = sym_addr(g_t);

    const int ew_blocks = (BATCH * TDIM) / 256;   // 16384
    const dim3 g_tt(TDIM / BN, BATCH / BM);       // (4, 64)  N=512 GEMMs
    const dim3 g_ft(FDIM / BN, BATCH / BM);       // (16, 64) N=2048 GEMMs

    h_kernel<<<ew_blocks, 256>>>(x, omega, phase);
    q0_kernel<<<ew_blocks, 256>>>(x, l1_w, l1_b);

    for (int i = 0; i < NATTN; i++) {
        ln_kernel<<<BATCH / 8, 256>>>(Q, alnqg + i * TDIM, alnqb + i * TDIM, h);
        gemm_bf16x3<1><<<g_tt, 256>>>(h, mu_w + (size_t)i * TDIM * TDIM,
                                      mu_b + i * TDIM, mu, BATCH, TDIM, TDIM);
        gemm_bf16x3<0><<<g_tt, 256>>>(h, sg_w + (size_t)i * TDIM * TDIM,
                                      sg_b + i * TDIM, sig, BATCH, TDIM, TDIM);
        attn_kernel<<<ew_blocks, 256>>>(G);
        ln_kernel<<<BATCH / 8, 256>>>(Q, alnfg + i * TDIM, alnfb + i * TDIM, h);
        gemm_bf16x3<2><<<g_ft, 256>>>(h, a_w1 + (size_t)i * FDIM * TDIM,
                                      a_b1 + i * FDIM, t, BATCH, FDIM, TDIM);
        gemm_bf16x3<3><<<g_tt, 256>>>(t, a_w2 + (size_t)i * TDIM * FDIM,
                                      a_b2 + i * TDIM, Q, BATCH, TDIM, FDIM);
    }
    for (int i = 0; i < NMLP; i++) {
        ln_kernel<<<BATCH / 8, 256>>>(Q, mln_g + i * TDIM, mln_b + i * TDIM, h);
        gemm_bf16x3<2><<<g_ft, 256>>>(h, m_w1 + (size_t)i * FDIM * TDIM,
                                      m_b1 + i * FDIM, t, BATCH, FDIM, TDIM);
        gemm_bf16x3<3><<<g_tt, 256>>>(t, m_w2 + (size_t)i * TDIM * FDIM,
                                      m_b2 + i * TDIM, Q, BATCH, TDIM, FDIM);
    }
    final_kernel<<<BATCH / 8, 256>>>(ro_w, ro_b, out);
}

// round 4
// speedup vs baseline: 1.2648x; 1.2648x over previous
#include <cuda_runtime.h>
#include <cuda_bf16.h>
#include <cstdint>
#include <math.h>

// ---------------------------------------------------------------------------
// Problem constants
// ---------------------------------------------------------------------------
#define BATCH 8192
#define TDIM  512
#define FDIM  2048
#define NATTN 4
#define NMLP  2

// weight scratch layout (element offsets into g_wh / g_wl)
#define MU_OFF  0
#define SG_OFF  1048576
#define AW1_OFF 2097152
#define AW2_OFF 6291456
#define MW1_OFF 10485760
#define MW2_OFF 12582912
#define WTOTAL  14680064

// ---------------------------------------------------------------------------
// Device scratch (static — no allocation at launch time)
// ---------------------------------------------------------------------------
__device__ __nv_bfloat16 g_wh[WTOTAL];        // 29 MB  weight hi
__device__ __nv_bfloat16 g_wl[WTOTAL];        // 29 MB  weight lo
__device__ float         g_Q [BATCH * TDIM];  // 16 MB  residual stream
__device__ float         g_mu[BATCH * TDIM];
__device__ float         g_sig[BATCH * TDIM];
__device__ __nv_bfloat16 g_hh[BATCH * TDIM];  // LN output hi
__device__ __nv_bfloat16 g_hl[BATCH * TDIM];  // LN output lo
__device__ __nv_bfloat16 g_th[BATCH * FDIM];  // FFN mid hi
__device__ __nv_bfloat16 g_tl[BATCH * FDIM];  // FFN mid lo

// ---------------------------------------------------------------------------
// Helpers
// ---------------------------------------------------------------------------
__device__ __forceinline__ float silu_f(float x) {
    return x / (1.0f + __expf(-x));
}

__device__ __forceinline__ void split_bf16(float x, __nv_bfloat16& hi, __nv_bfloat16& lo) {
    hi = __float2bfloat16_rn(x);
    lo = __float2bfloat16_rn(x - __bfloat162float(hi));
}

__device__ __forceinline__ void mma_bf16(float* d, const uint32_t* a, const uint32_t* b) {
    asm volatile(
        "mma.sync.aligned.m16n8k16.row.col.f32.bf16.bf16.f32 "
        "{%0,%1,%2,%3}, {%4,%5,%6,%7}, {%8,%9}, {%0,%1,%2,%3};\n"
        : "+f"(d[0]), "+f"(d[1]), "+f"(d[2]), "+f"(d[3])
        : "r"(a[0]), "r"(a[1]), "r"(a[2]), "r"(a[3]), "r"(b[0]), "r"(b[1]));
}

__device__ __forceinline__ void cp16(uint32_t dst, const void* src) {
    asm volatile("cp.async.cg.shared.global [%0], [%1], 16;\n" :: "r"(dst), "l"(src));
}
__device__ __forceinline__ void cp_commit() {
    asm volatile("cp.async.commit_group;\n");
}
template<int N> __device__ __forceinline__ void cp_wait() {
    asm volatile("cp.async.wait_group %0;\n" :: "n"(N));
}

__device__ __forceinline__ void ldsm4(uint32_t& r0, uint32_t& r1, uint32_t& r2,
                                      uint32_t& r3, uint32_t addr) {
    asm volatile("ldmatrix.sync.aligned.m8n8.x4.shared.b16 {%0,%1,%2,%3}, [%4];\n"
                 : "=r"(r0), "=r"(r1), "=r"(r2), "=r"(r3) : "r"(addr));
}

// ---------------------------------------------------------------------------
// bf16x3 split GEMM, pre-split operands, cp.async double buffer, ldmatrix.
//   C[M,N] = epi(A[M,K] @ W[N,K]^T + bias),  A = Ah+Al, W = Wh+Wl (bf16 pairs)
//   acc += Ah*Wh + Ah*Wl + Al*Wh   (lo*lo dropped, ~2^-18 relative)
// EPI: 0 = bias, 1 = tanh, 2 = silu -> bf16 hi/lo pair output, 3 = +C residual
// Tiles: BM=BN=128, BK=32; 256 thr = 8 warps (2m x 4n), warp tile 64x32.
// smem row layout: 16 uint32 (32 bf16) + 4 pad = stride 20 -> ldmatrix
// 8-row groups hit banks {0,20,8,28,16,4,24,12}+[0,4) : conflict-free.
// ---------------------------------------------------------------------------
#define BM 128
#define BN 128
#define BK 32
#define SSTR 20
#define ARR_BYTES   (128 * SSTR * 4)   // 10240
#define STAGE_BYTES (4 * ARR_BYTES)    // 40960: Ahi, Alo, Whi, Wlo
#define SMEM_BYTES  (2 * STAGE_BYTES)  // 81920

template<int EPI>
__global__ __launch_bounds__(256, 2) void gemm_bf16p(
    const __nv_bfloat16* __restrict__ Ah, const __nv_bfloat16* __restrict__ Al,
    const __nv_bfloat16* __restrict__ Wh, const __nv_bfloat16* __restrict__ Wl,
    const float* __restrict__ bias, float* __restrict__ C,
    __nv_bfloat16* __restrict__ Ch, __nv_bfloat16* __restrict__ Cl,
    int M, int N, int K)
{
    extern __shared__ uint32_t smem[];
    const uint32_t sb = (uint32_t)__cvta_generic_to_shared(smem);

    const int tid  = threadIdx.x;
    const int lane = tid & 31;
    const int warp = tid >> 5;
    const int warpM = warp & 1;
    const int warpN = warp >> 1;
    const int g  = lane >> 2;
    const int tg = lane & 3;

    const int rowBase = blockIdx.y * BM;
    const int colBase = blockIdx.x * BN;

    // staging source base pointers for this thread's two 16B chunks per array
    const int c0  = tid;            // chunk ids: tid and tid+256
    const int c1  = tid + 256;
    const int r0s = c0 >> 2, q0s = c0 & 3;
    const int r1s = c1 >> 2, q1s = c1 & 3;

    float acc[4][4][4];
#pragma unroll
    for (int mi = 0; mi < 4; mi++)
#pragma unroll
        for (int ni = 0; ni < 4; ni++)
#pragma unroll
            for (int r = 0; r < 4; r++) acc[mi][ni][r] = 0.0f;

    const int ntiles = K / BK;

    // ---- stage k-tile `kt` into buffer `s` ----
    auto stage = [&](int s, int kt) {
        const int k0 = kt * BK;
        uint32_t base = sb + s * STAGE_BYTES;
        {
            uint32_t off = r0s * (SSTR * 4) + q0s * 16;
            size_t ga = (size_t)(rowBase + r0s) * K + k0 + q0s * 8;
            size_t gw = (size_t)(colBase + r0s) * K + k0 + q0s * 8;
            cp16(base + 0 * ARR_BYTES + off, Ah + ga);
            cp16(base + 1 * ARR_BYTES + off, Al + ga);
            cp16(base + 2 * ARR_BYTES + off, Wh + gw);
            cp16(base + 3 * ARR_BYTES + off, Wl + gw);
        }
        {
            uint32_t off = r1s * (SSTR * 4) + q1s * 16;
            size_t ga = (size_t)(rowBase + r1s) * K + k0 + q1s * 8;
            size_t gw = (size_t)(colBase + r1s) * K + k0 + q1s * 8;
            cp16(base + 0 * ARR_BYTES + off, Ah + ga);
            cp16(base + 1 * ARR_BYTES + off, Al + ga);
            cp16(base + 2 * ARR_BYTES + off, Wh + gw);
            cp16(base + 3 * ARR_BYTES + off, Wl + gw);
        }
    };

    // ldmatrix per-lane address pieces (shared across tiles)
    const int ldrow = lane & 15;                 // row within 16-row tile
    const uint32_t ldcol = ((lane >> 4) << 2);   // uint32 col: 0 or 4 (k half)

    stage(0, 0);
    cp_commit();

    for (int it = 0; it < ntiles; it++) {
        if (it + 1 < ntiles) {
            stage((it + 1) & 1, it + 1);
            cp_commit();
            cp_wait<1>();
        } else {
            cp_wait<0>();
        }
        __syncthreads();

        const uint32_t base = sb + (it & 1) * STAGE_BYTES;
#pragma unroll
        for (int kc = 0; kc < 2; kc++) {
            const uint32_t kk = kc * 8;
            uint32_t bhi[4][2], blo[4][2];
#pragma unroll
            for (int p = 0; p < 2; p++) {
                int nrow = warpN * 32 + p * 16 + ldrow;
                uint32_t off = nrow * (SSTR * 4) + (kk + ldcol) * 4;
                uint32_t r0, r1, r2, r3;
                ldsm4(r0, r1, r2, r3, base + 2 * ARR_BYTES + off);
                bhi[2 * p][0] = r0; bhi[2 * p + 1][0] = r1;
                bhi[2 * p][1] = r2; bhi[2 * p + 1][1] = r3;
                ldsm4(r0, r1, r2, r3, base + 3 * ARR_BYTES + off);
                blo[2 * p][0] = r0; blo[2 * p + 1][0] = r1;
                blo[2 * p][1] = r2; blo[2 * p + 1][1] = r3;
            }
#pragma unroll
            for (int mi = 0; mi < 4; mi++) {
                int arow = warpM * 64 + mi * 16 + ldrow;
                uint32_t off = arow * (SSTR * 4) + (kk + ldcol) * 4;
                uint32_t ah[4], al[4];
                ldsm4(ah[0], ah[1], ah[2], ah[3], base + 0 * ARR_BYTES + off);
                ldsm4(al[0], al[1], al[2], al[3], base + 1 * ARR_BYTES + off);
#pragma unroll
                for (int ni = 0; ni < 4; ni++) {
                    mma_bf16(acc[mi][ni], ah, bhi[ni]);
                    mma_bf16(acc[mi][ni], ah, blo[ni]);
                    mma_bf16(acc[mi][ni], al, bhi[ni]);
                }
            }
        }
        __syncthreads();
    }

    // ---- epilogue ----
#pragma unroll
    for (int mi = 0; mi < 4; mi++) {
#pragma unroll
        for (int ni = 0; ni < 4; ni++) {
            int m0 = rowBase + warpM * 64 + mi * 16 + g;
            int n0 = colBase + warpN * 32 + ni * 8 + tg * 2;
            float bn0 = bias[n0], bn1 = bias[n0 + 1];
#pragma unroll
            for (int h = 0; h < 2; h++) {
                int m = m0 + h * 8;
                float v0 = acc[mi][ni][2 * h + 0] + bn0;
                float v1 = acc[mi][ni][2 * h + 1] + bn1;
                size_t idx = (size_t)m * N + n0;
                if (EPI == 1) {
                    v0 = tanhf(v0); v1 = tanhf(v1);
                    C[idx] = v0; C[idx + 1] = v1;
                } else if (EPI == 2) {
                    v0 = silu_f(v0); v1 = silu_f(v1);
                    __nv_bfloat16 h0, l0, h1, l1;
                    split_bf16(v0, h0, l0);
                    split_bf16(v1, h1, l1);
                    *(__nv_bfloat162*)(Ch + idx) = __halves2bfloat162(h0, h1);
                    *(__nv_bfloat162*)(Cl + idx) = __halves2bfloat162(l0, l1);
                } else if (EPI == 3) {
                    C[idx]     = v0 + C[idx];
                    C[idx + 1] = v1 + C[idx + 1];
                } else {
                    C[idx] = v0; C[idx + 1] = v1;
                }
            }
        }
    }
}

// ---------------------------------------------------------------------------
// Weight split: fp32 -> bf16 hi/lo
// ---------------------------------------------------------------------------
__global__ __launch_bounds__(256) void wsplit_kernel(
    const float* __restrict__ src, __nv_bfloat16* __restrict__ hi,
    __nv_bfloat16* __restrict__ lo)
{
    int i = blockIdx.x * 256 + threadIdx.x;
    float v = src[i];
    __nv_bfloat16 h, l;
    split_bf16(v, h, l);
    hi[i] = h; lo[i] = l;
}

// ---------------------------------------------------------------------------
// Q0 = silu(x @ l1_w^T + l1_b)
// ---------------------------------------------------------------------------
__global__ __launch_bounds__(256) void q0_kernel(
    const float* __restrict__ x, const float* __restrict__ w,
    const float* __restrict__ bias)
{
    int idx = blockIdx.x * 256 + threadIdx.x;     // b*T + t
    int b = idx >> 9, t = idx & 511;
    float p = fmaf(x[b * 2 + 0], w[t * 2 + 0],
              fmaf(x[b * 2 + 1], w[t * 2 + 1], bias[t]));
    g_Q[idx] = silu_f(p);
}

// ---------------------------------------------------------------------------
// LayerNorm over T=512, one warp per row; outputs bf16 hi/lo split
// ---------------------------------------------------------------------------
__global__ __launch_bounds__(256) void ln_kernel(
    const float* __restrict__ X, const float* __restrict__ gam,
    const float* __restrict__ bet)
{
    int warp = threadIdx.x >> 5, lane = threadIdx.x & 31;
    int row = blockIdx.x * 8 + warp;
    const float4* xr = (const float4*)(X + (size_t)row * 512);
    float4 v[4];
    float s = 0.0f;
#pragma unroll
    for (int j = 0; j < 4; j++) {
        v[j] = xr[lane + j * 32];
        s += v[j].x + v[j].y + v[j].z + v[j].w;
    }
#pragma unroll
    for (int o = 16; o > 0; o >>= 1) s += __shfl_xor_sync(0xffffffffu, s, o);
    float m = s * (1.0f / 512.0f);
    float vs = 0.0f;
#pragma unroll
    for (int j = 0; j < 4; j++) {
        float dx = v[j].x - m, dy = v[j].y - m, dz = v[j].z - m, dw = v[j].w - m;
        vs += dx * dx + dy * dy + dz * dz + dw * dw;
    }
#pragma unroll
    for (int o = 16; o > 0; o >>= 1) vs += __shfl_xor_sync(0xffffffffu, vs, o);
    float inv = rsqrtf(vs * (1.0f / 512.0f) + 1e-5f);

    __nv_bfloat162* yh = (__nv_bfloat162*)(g_hh + (size_t)row * 512);
    __nv_bfloat162* yl = (__nv_bfloat162*)(g_hl + (size_t)row * 512);
    const float4* gr = (const float4*)gam;
    const float4* br = (const float4*)bet;
#pragma unroll
    for (int j = 0; j < 4; j++) {
        int c = lane + j * 32;
        float4 gg = gr[c], bb = br[c];
        float o0 = (v[j].x - m) * inv * gg.x + bb.x;
        float o1 = (v[j].y - m) * inv * gg.y + bb.y;
        float o2 = (v[j].z - m) * inv * gg.z + bb.z;
        float o3 = (v[j].w - m) * inv * gg.w + bb.w;
        __nv_bfloat16 h0, l0, h1, l1, h2, l2, h3, l3;
        split_bf16(o0, h0, l0); split_bf16(o1, h1, l1);
        split_bf16(o2, h2, l2); split_bf16(o3, h3, l3);
        yh[c * 2    ] = __halves2bfloat162(h0, h1);
        yh[c * 2 + 1] = __halves2bfloat162(h2, h3);
        yl[c * 2    ] = __halves2bfloat162(l0, l1);
        yl[c * 2 + 1] = __halves2bfloat162(l2, l3);
    }
}

// ---------------------------------------------------------------------------
// Attention gather with inline RFF recompute:
//   Q[b,n] += sum_k exp(-0.5 (G[n,k]-mu)^2/(sig^2+eps)) * cos(omega.x + phase)
// ---------------------------------------------------------------------------
__global__ __launch_bounds__(256) void attn_kernel(
    const float* __restrict__ x, const float* __restrict__ omega,
    const float* __restrict__ phase, const float* __restrict__ G)
{
    int idx = blockIdx.x * 256 + threadIdx.x;     // b*T + n
    int b = idx >> 9, n = idx & 511;
    float x0 = x[b * 2 + 0], x1 = x[b * 2 + 1];
    float mu = g_mu[idx], sg = g_sig[idx];
    float rs = 1.0f / fmaf(sg, sg, 1e-8f);
    float acc = 0.0f;
#pragma unroll
    for (int k = 0; k < 8; k++) {
        int nk = n * 8 + k;
        float arg = fmaf(omega[nk * 2 + 0], x0,
                    fmaf(omega[nk * 2 + 1], x1, phase[nk]));
        float hv = cosf(arg);
        float d = G[nk] - mu;
        acc += __expf(-0.5f * d * d * rs) * hv;
    }
    g_Q[idx] += acc;
}

// ---------------------------------------------------------------------------
// Readout: out[b] = sum_t silu(Q[b,t]) * ro_w[t] + ro_b
// ---------------------------------------------------------------------------
__global__ __launch_bounds__(256) void final_kernel(
    const float* __restrict__ ro_w, const float* __restrict__ ro_b,
    float* __restrict__ out)
{
    int warp = threadIdx.x >> 5, lane = threadIdx.x & 31;
    int row = blockIdx.x * 8 + warp;
    const float4* q4 = (const float4*)(g_Q + (size_t)row * 512);
    const float4* w4 = (const float4*)ro_w;
    float s = 0.0f;
#pragma unroll
    for (int j = 0; j < 4; j++) {
        int c = lane + j * 32;
        float4 q = q4[c], w = w4[c];
        s += silu_f(q.x) * w.x + silu_f(q.y) * w.y
           + silu_f(q.z) * w.z + silu_f(q.w) * w.w;
    }
#pragma unroll
    for (int o = 16; o > 0; o >>= 1) s += __shfl_xor_sync(0xffffffffu, s, o);
    if (lane == 0) out[row] = s + ro_b[0];
}

// ---------------------------------------------------------------------------
// Host launcher
// ---------------------------------------------------------------------------
template<typename T>
static T* sym_addr(const T& sym) {
    void* p = nullptr;
    cudaGetSymbolAddress(&p, sym);
    return (T*)p;
}

extern "C" void kernel_launch(void* const* d_in, const int* in_sizes, int n_in,
                              void* d_out, int out_size)
{
    const float* x      = (const float*)d_in[0];
    const float* omega  = (const float*)d_in[1];
    const float* G      = (const float*)d_in[2];
    const float* phase  = (const float*)d_in[3];
    const float* l1_w   = (const float*)d_in[4];
    const float* l1_b   = (const float*)d_in[5];
    const float* mu_w   = (const float*)d_in[6];
    const float* mu_b   = (const float*)d_in[7];
    const float* sg_w   = (const float*)d_in[8];
    const float* sg_b   = (const float*)d_in[9];
    const float* alnqg  = (const float*)d_in[10];
    const float* alnqb  = (const float*)d_in[11];
    const float* alnfg  = (const float*)d_in[12];
    const float* alnfb  = (const float*)d_in[13];
    const float* a_w1   = (const float*)d_in[14];
    const float* a_b1   = (const float*)d_in[15];
    const float* a_w2   = (const float*)d_in[16];
    const float* a_b2   = (const float*)d_in[17];
    const float* mln_g  = (const float*)d_in[18];
    const float* mln_b  = (const float*)d_in[19];
    const float* m_w1   = (const float*)d_in[20];
    const float* m_b1   = (const float*)d_in[21];
    const float* m_w2   = (const float*)d_in[22];
    const float* m_b2   = (const float*)d_in[23];
    const float* ro_w   = (const float*)d_in[24];
    const float* ro_b   = (const float*)d_in[25];
    float* out = (float*)d_out;

    __nv_bfloat16* wh = nullptr; __nv_bfloat16* wl = nullptr;
    float* Q = nullptr; float* mu = nullptr; float* sig = nullptr;
    __nv_bfloat16* hh = nullptr; __nv_bfloat16* hl = nullptr;
    __nv_bfloat16* th = nullptr; __nv_bfloat16* tl = nullptr;
    {
        void* p;
        cudaGetSymbolAddress(&p, g_wh); wh = (__nv_bfloat16*)p;
        cudaGetSymbolAddress(&p, g_wl); wl = (__nv_bfloat16*)p;
        cudaGetSymbolAddress(&p, g_Q);  Q  = (float*)p;
        cudaGetSymbolAddress(&p, g_mu); mu = (float*)p;
        cudaGetSymbolAddress(&p, g_sig); sig = (float*)p;
        cudaGetSymbolAddress(&p, g_hh); hh = (__nv_bfloat16*)p;
        cudaGetSymbolAddress(&p, g_hl); hl = (__nv_bfloat16*)p;
        cudaGetSymbolAddress(&p, g_th); th = (__nv_bfloat16*)p;
        cudaGetSymbolAddress(&p, g_tl); tl = (__nv_bfloat16*)p;
    }

    static bool attr_set = false;
    if (!attr_set) {
        cudaFuncSetAttribute(gemm_bf16p<0>, cudaFuncAttributeMaxDynamicSharedMemorySize, SMEM_BYTES);
        cudaFuncSetAttribute(gemm_bf16p<1>, cudaFuncAttributeMaxDynamicSharedMemorySize, SMEM_BYTES);
        cudaFuncSetAttribute(gemm_bf16p<2>, cudaFuncAttributeMaxDynamicSharedMemorySize, SMEM_BYTES);
        cudaFuncSetAttribute(gemm_bf16p<3>, cudaFuncAttributeMaxDynamicSharedMemorySize, SMEM_BYTES);
        attr_set = true;
    }

    const int ew_blocks = (BATCH * TDIM) / 256;   // 16384
    const dim3 g_tt(TDIM / BN, BATCH / BM);       // (4, 64)
    const dim3 g_ft(FDIM / BN, BATCH / BM);       // (16, 64)

    // weight pre-split (runs every replay; ~30us of bandwidth)
    wsplit_kernel<<<(NATTN * TDIM * TDIM) / 256, 256>>>(mu_w, wh + MU_OFF,  wl + MU_OFF);
    wsplit_kernel<<<(NATTN * TDIM * TDIM) / 256, 256>>>(sg_w, wh + SG_OFF,  wl + SG_OFF);
    wsplit_kernel<<<(NATTN * FDIM * TDIM) / 256, 256>>>(a_w1, wh + AW1_OFF, wl + AW1_OFF);
    wsplit_kernel<<<(NATTN * TDIM * FDIM) / 256, 256>>>(a_w2, wh + AW2_OFF, wl + AW2_OFF);
    wsplit_kernel<<<(NMLP  * FDIM * TDIM) / 256, 256>>>(m_w1, wh + MW1_OFF, wl + MW1_OFF);
    wsplit_kernel<<<(NMLP  * TDIM * FDIM) / 256, 256>>>(m_w2, wh + MW2_OFF, wl + MW2_OFF);

    q0_kernel<<<ew_blocks, 256>>>(x, l1_w, l1_b);

    for (int i = 0; i < NATTN; i++) {
        const size_t wtt = (size_t)i * TDIM * TDIM;
        const size_t wft = (size_t)i * FDIM * TDIM;
        ln_kernel<<<BATCH / 8, 256>>>(Q, alnqg + i * TDIM, alnqb + i * TDIM);
        gemm_bf16p<1><<<g_tt, 256, SMEM_BYTES>>>(hh, hl, wh + MU_OFF + wtt, wl + MU_OFF + wtt,
                                                 mu_b + i * TDIM, mu, nullptr, nullptr,
                                                 BATCH, TDIM, TDIM);
        gemm_bf16p<0><<<g_tt, 256, SMEM_BYTES>>>(hh, hl, wh + SG_OFF + wtt, wl + SG_OFF + wtt,
                                                 sg_b + i * TDIM, sig, nullptr, nullptr,
                                                 BATCH, TDIM, TDIM);
        attn_kernel<<<ew_blocks, 256>>>(x, omega, phase, G);
        ln_kernel<<<BATCH / 8, 256>>>(Q, alnfg + i * TDIM, alnfb + i * TDIM);
        gemm_bf16p<2><<<g_ft, 256, SMEM_BYTES>>>(hh, hl, wh + AW1_OFF + wft, wl + AW1_OFF + wft,
                                                 a_b1 + i * FDIM, nullptr, th, tl,
                                                 BATCH, FDIM, TDIM);
        gemm_bf16p<3><<<g_tt, 256, SMEM_BYTES>>>(th, tl, wh + AW2_OFF + wft, wl + AW2_OFF + wft,
                                                 a_b2 + i * TDIM, Q, nullptr, nullptr,
                                                 BATCH, TDIM, FDIM);
    }
    for (int i = 0; i < NMLP; i++) {
        const size_t wft = (size_t)i * FDIM * TDIM;
        ln_kernel<<<BATCH / 8, 256>>>(Q, mln_g + i * TDIM, mln_b + i * TDIM);
        gemm_bf16p<2><<<g_ft, 256, SMEM_BYTES>>>(hh, hl, wh + MW1_OFF + wft, wl + MW1_OFF + wft,
                                                 m_b1 + i * FDIM, nullptr, th, tl,
                                                 BATCH, FDIM, TDIM);
        gemm_bf16p<3><<<g_tt, 256, SMEM_BYTES>>>(th, tl, wh + MW2_OFF + wft, wl + MW2_OFF + wft,
                                                 m_b2 + i * TDIM, Q, nullptr, nullptr,
                                                 BATCH, TDIM, FDIM);
    }
    final_kernel<<<BATCH / 8, 256>>>(ro_w, ro_b, out);
}